// round 3
// baseline (speedup 1.0000x reference)
#include <cuda_runtime.h>

#define N_NODES 100000
#define N_EDGES 800000
#define HID     128
#define NGRAPH  128
#define NCLS    10
#define BN_EPS  1e-5f

// ---------------- scratch (allocation-free: device globals) ----------------
__device__ __align__(16) float g_agg[N_NODES * HID];   // aggregate buffer (self + neighbor sum)
__device__ __align__(16) float g_tmp[N_NODES * HID];   // MLP hidden
__device__ __align__(16) float g_h  [N_NODES * HID];   // conv output / BN output
__device__ __align__(16) float g_stats[4 * HID];       // [sum1, sumsq1, sum2, sumsq2]
__device__ __align__(16) float g_pool[NGRAPH * HID];
__device__            float g_cnt[NGRAPH];
__device__ int g_idx64;    // 1 if edge_index buffer is int64, 0 if int32
__device__ int g_batch64;  // same for batch

// ---------------- dtype detection (indices valid iff interpreted with right width) ----
__global__ void detect_kernel(const void* eidx, const void* batch) {
    if (threadIdx.x == 0) {
        const long long* p = (const long long*)eidx;
        int ok = 1;
        for (int i = 0; i < 64; i++) {
            long long v = p[i];
            if (v < 0 || v >= N_NODES) { ok = 0; break; }
        }
        g_idx64 = ok;
        // batch is sorted; mid-array entries are nonzero under both encodings,
        // and mid int64-reads stay in bounds even if the buffer is int32-sized.
        const long long* q = (const long long*)batch;
        int ok2 = 1;
        for (int i = N_NODES / 2 - 64; i < N_NODES / 2; i++) {
            long long v = q[i];
            if (v < 0 || v >= NGRAPH) { ok2 = 0; break; }
        }
        g_batch64 = ok2;
    }
}

__device__ __forceinline__ int load_index(const void* p, unsigned i, int is64) {
    return is64 ? (int)((const long long*)p)[i] : ((const int*)p)[i];
}

// ---------------- zero the accumulators ----------------
__global__ void zero_kernel() {
    int i = blockIdx.x * blockDim.x + threadIdx.x;
    if (i < NGRAPH * HID) g_pool[i] = 0.f;
    if (i < 4 * HID)      g_stats[i] = 0.f;
    if (i < NGRAPH)       g_cnt[i] = 0.f;
}

// ---------------- copy x -> g_agg (self term, eps=0 so (1+eps)=1) ----------------
__global__ void copy_kernel(const float4* __restrict__ src) {
    int i = blockIdx.x * 256 + threadIdx.x;
    if (i < N_NODES * (HID / 4)) ((float4*)g_agg)[i] = src[i];
}

// ---------------- edge scatter: g_agg[dst] += feat[src], 32 float4 per edge ----------------
__global__ void scatter_kernel(const float* __restrict__ feat, const void* __restrict__ eidx) {
    unsigned idx = blockIdx.x * 256u + threadIdx.x;
    unsigned e = idx >> 5;
    if (e >= N_EDGES) return;
    unsigned c = idx & 31u;
    int is64 = g_idx64;
    int s = load_index(eidx, e, is64);
    int d = load_index(eidx, N_EDGES + e, is64);
    float4 v = ((const float4*)feat)[s * 32 + c];
    atomicAdd(((float4*)g_agg) + (d * 32 + c), v);
}

// ---------------- GEMM: C[M,128] = act(A[M,128] @ W[128,128] + b) ----------------
// block = 256 threads, tile = 64 rows x 128 cols, full W resident in SMEM.
template <bool RELU>
__global__ void gemm_kernel(const float* __restrict__ A, const float* __restrict__ W,
                            const float* __restrict__ bias, float* __restrict__ C) {
    extern __shared__ float sm[];
    float* sW = sm;                 // 128*128
    float* sA = sm + HID * HID;     // 64*128
    int t = threadIdx.x;

    const float4* W4 = (const float4*)W;
    float4* sW4 = (float4*)sW;
#pragma unroll
    for (int i = 0; i < 16; i++) sW4[t + i * 256] = W4[t + i * 256];

    int row0 = blockIdx.x * 64;
    int rows = N_NODES - row0; if (rows > 64) rows = 64;
    const float4* A4 = (const float4*)(A + (size_t)row0 * HID);
    float4* sA4 = (float4*)sA;
#pragma unroll
    for (int i = 0; i < 8; i++) {
        int idx = t + i * 256;
        int r = idx >> 5;
        sA4[idx] = (r < rows) ? A4[idx] : make_float4(0.f, 0.f, 0.f, 0.f);
    }
    __syncthreads();

    int cx = (t & 31) * 4;   // output column start (float4)
    int ry = (t >> 5) * 8;   // output row start (8 rows per thread)
    float acc[8][4] = {};

#pragma unroll 4
    for (int k = 0; k < HID; k++) {
        float4 w = *(const float4*)&sW[k * HID + cx];
#pragma unroll
        for (int r = 0; r < 8; r++) {
            float a = sA[(ry + r) * HID + k];   // warp-uniform broadcast
            acc[r][0] += a * w.x;
            acc[r][1] += a * w.y;
            acc[r][2] += a * w.z;
            acc[r][3] += a * w.w;
        }
    }

    float4 b4 = *(const float4*)&bias[cx];
#pragma unroll
    for (int r = 0; r < 8; r++) {
        if (ry + r < rows) {
            float4 o;
            o.x = acc[r][0] + b4.x;
            o.y = acc[r][1] + b4.y;
            o.z = acc[r][2] + b4.z;
            o.w = acc[r][3] + b4.w;
            if (RELU) {
                o.x = fmaxf(o.x, 0.f); o.y = fmaxf(o.y, 0.f);
                o.z = fmaxf(o.z, 0.f); o.w = fmaxf(o.w, 0.f);
            }
            *(float4*)&C[(size_t)(row0 + ry + r) * HID + cx] = o;
        }
    }
}

// ---------------- per-column sum / sumsq over nodes ----------------
__global__ void colstats_kernel(const float* __restrict__ h, int stat_off) {
    int f = threadIdx.x;   // 128 threads
    float s = 0.f, q = 0.f;
    for (int r = blockIdx.x; r < N_NODES; r += gridDim.x) {
        float v = h[(size_t)r * HID + f];
        s += v;
        q += v * v;
    }
    atomicAdd(&g_stats[stat_off + f], s);
    atomicAdd(&g_stats[stat_off + HID + f], q);
}

// ---------------- BN1 apply + relu: write g_h (in place) and g_agg (self-term copy) ----------------
__global__ void bn_apply1_kernel(const float* __restrict__ gamma, const float* __restrict__ beta) {
    int i = blockIdx.x * 256 + threadIdx.x;      // float4 index
    if (i >= N_NODES * 32) return;
    int c4 = i & 31;
    const float inv_n = 1.f / (float)N_NODES;
    float4 sum4 = ((const float4*)g_stats)[c4];
    float4 sq4  = ((const float4*)g_stats)[32 + c4];
    float4 gm4  = ((const float4*)gamma)[c4];
    float4 bt4  = ((const float4*)beta)[c4];
    float4 v = ((float4*)g_h)[i];
    float4 y;
    {
        float m = sum4.x * inv_n; float var = sq4.x * inv_n - m * m;
        y.x = fmaxf((v.x - m) * rsqrtf(var + BN_EPS) * gm4.x + bt4.x, 0.f);
        m = sum4.y * inv_n; var = sq4.y * inv_n - m * m;
        y.y = fmaxf((v.y - m) * rsqrtf(var + BN_EPS) * gm4.y + bt4.y, 0.f);
        m = sum4.z * inv_n; var = sq4.z * inv_n - m * m;
        y.z = fmaxf((v.z - m) * rsqrtf(var + BN_EPS) * gm4.z + bt4.z, 0.f);
        m = sum4.w * inv_n; var = sq4.w * inv_n - m * m;
        y.w = fmaxf((v.w - m) * rsqrtf(var + BN_EPS) * gm4.w + bt4.w, 0.f);
    }
    ((float4*)g_h)[i] = y;
    ((float4*)g_agg)[i] = y;
}

// ---------------- BN2 apply + relu + fused per-graph pooled sum ----------------
__global__ void bn_apply2_kernel(const float* __restrict__ gamma, const float* __restrict__ beta,
                                 const void* __restrict__ batch) {
    int i = blockIdx.x * 256 + threadIdx.x;
    if (i >= N_NODES * 32) return;
    int c4 = i & 31;
    int row = i >> 5;
    const float inv_n = 1.f / (float)N_NODES;
    float4 sum4 = ((const float4*)g_stats)[64 + c4];
    float4 sq4  = ((const float4*)g_stats)[96 + c4];
    float4 gm4  = ((const float4*)gamma)[c4];
    float4 bt4  = ((const float4*)beta)[c4];
    float4 v = ((float4*)g_h)[i];
    float4 y;
    {
        float m = sum4.x * inv_n; float var = sq4.x * inv_n - m * m;
        y.x = fmaxf((v.x - m) * rsqrtf(var + BN_EPS) * gm4.x + bt4.x, 0.f);
        m = sum4.y * inv_n; var = sq4.y * inv_n - m * m;
        y.y = fmaxf((v.y - m) * rsqrtf(var + BN_EPS) * gm4.y + bt4.y, 0.f);
        m = sum4.z * inv_n; var = sq4.z * inv_n - m * m;
        y.z = fmaxf((v.z - m) * rsqrtf(var + BN_EPS) * gm4.z + bt4.z, 0.f);
        m = sum4.w * inv_n; var = sq4.w * inv_n - m * m;
        y.w = fmaxf((v.w - m) * rsqrtf(var + BN_EPS) * gm4.w + bt4.w, 0.f);
    }
    int b = load_index(batch, (unsigned)row, g_batch64);
    atomicAdd(((float4*)g_pool) + (b * 32 + c4), y);
}

// ---------------- per-graph node counts ----------------
__global__ void counts_kernel(const void* __restrict__ batch) {
    __shared__ int hist[NGRAPH];
    if (threadIdx.x < NGRAPH) hist[threadIdx.x] = 0;
    __syncthreads();
    int is64 = g_batch64;
    for (int i = blockIdx.x * 256 + threadIdx.x; i < N_NODES; i += gridDim.x * 256)
        atomicAdd(&hist[load_index(batch, (unsigned)i, is64)], 1);
    __syncthreads();
    if (threadIdx.x < NGRAPH && hist[threadIdx.x])
        atomicAdd(&g_cnt[threadIdx.x], (float)hist[threadIdx.x]);
}

// ---------------- head: mean pool -> linear -> log_softmax ----------------
__global__ void head_kernel(const float* __restrict__ Wlin, const float* __restrict__ blin,
                            float* __restrict__ out) {
    __shared__ float p[HID];
    __shared__ float logit[NCLS];
    int g = blockIdx.x;
    float c = fmaxf(g_cnt[g], 1.0f);
    p[threadIdx.x] = g_pool[g * HID + threadIdx.x] / c;
    __syncthreads();
    if (threadIdx.x < NCLS) {
        float s = blin[threadIdx.x];
        for (int k = 0; k < HID; k++) s += p[k] * Wlin[k * NCLS + threadIdx.x];
        logit[threadIdx.x] = s;
    }
    __syncthreads();
    if (threadIdx.x == 0) {
        float m = -1e30f;
        for (int i = 0; i < NCLS; i++) m = fmaxf(m, logit[i]);
        float se = 0.f;
        for (int i = 0; i < NCLS; i++) se += expf(logit[i] - m);
        float lse = m + logf(se);
        for (int i = 0; i < NCLS; i++) out[g * NCLS + i] = logit[i] - lse;
    }
}

// ---------------- launch ----------------
extern "C" void kernel_launch(void* const* d_in, const int* in_sizes, int n_in,
                              void* d_out, int out_size) {
    const float* x     = (const float*)d_in[0];
    const void*  eidx  = d_in[1];
    const void*  batch = d_in[2];
    const float* W1a = (const float*)d_in[3];
    const float* b1a = (const float*)d_in[4];
    const float* W1b = (const float*)d_in[5];
    const float* b1b = (const float*)d_in[6];
    const float* gamma1 = (const float*)d_in[7];
    const float* beta1  = (const float*)d_in[8];
    const float* W2a = (const float*)d_in[9];
    const float* b2a = (const float*)d_in[10];
    const float* W2b = (const float*)d_in[11];
    const float* b2b = (const float*)d_in[12];
    const float* gamma2 = (const float*)d_in[13];
    const float* beta2  = (const float*)d_in[14];
    const float* Wlin = (const float*)d_in[15];
    const float* blin = (const float*)d_in[16];
    float* out = (float*)d_out;

    float *p_agg, *p_tmp, *p_h;
    cudaGetSymbolAddress((void**)&p_agg, g_agg);
    cudaGetSymbolAddress((void**)&p_tmp, g_tmp);
    cudaGetSymbolAddress((void**)&p_h,   g_h);

    const int SMEM = (HID * HID + 64 * HID) * sizeof(float);   // 96 KB
    cudaFuncSetAttribute(gemm_kernel<true>,  cudaFuncAttributeMaxDynamicSharedMemorySize, SMEM);
    cudaFuncSetAttribute(gemm_kernel<false>, cudaFuncAttributeMaxDynamicSharedMemorySize, SMEM);

    const int EW_BLOCKS   = (N_NODES * 32 + 255) / 256;   // element-wise (float4) passes
    const int SC_BLOCKS   = (N_EDGES * 32 + 255) / 256;   // scatter
    const int GEMM_BLOCKS = (N_NODES + 63) / 64;

    detect_kernel<<<1, 32>>>(eidx, batch);
    zero_kernel<<<64, 256>>>();

    // ---- conv1 ----
    copy_kernel<<<EW_BLOCKS, 256>>>((const float4*)x);
    scatter_kernel<<<SC_BLOCKS, 256>>>(x, eidx);
    gemm_kernel<true ><<<GEMM_BLOCKS, 256, SMEM>>>(p_agg, W1a, b1a, p_tmp);
    gemm_kernel<false><<<GEMM_BLOCKS, 256, SMEM>>>(p_tmp, W1b, b1b, p_h);
    colstats_kernel<<<1024, 128>>>(p_h, 0);
    bn_apply1_kernel<<<EW_BLOCKS, 256>>>(gamma1, beta1);

    // ---- conv2 ----
    scatter_kernel<<<SC_BLOCKS, 256>>>(p_h, eidx);
    gemm_kernel<true ><<<GEMM_BLOCKS, 256, SMEM>>>(p_agg, W2a, b2a, p_tmp);
    gemm_kernel<false><<<GEMM_BLOCKS, 256, SMEM>>>(p_tmp, W2b, b2b, p_h);
    colstats_kernel<<<1024, 128>>>(p_h, 2 * HID);
    counts_kernel<<<128, 256>>>(batch);
    bn_apply2_kernel<<<EW_BLOCKS, 256>>>(gamma2, beta2, batch);

    // ---- head ----
    head_kernel<<<NGRAPH, HID>>>(Wlin, blin, out);
}

// round 5
// speedup vs baseline: 1.4883x; 1.4883x over previous
#include <cuda_runtime.h>
#include <cstdint>

#define N_NODES 100000
#define N_EDGES 800000
#define HID     128
#define NGRAPH  128
#define NCLS    10
#define BN_EPS  1e-5f
#define MT      128        // M rows per MLP block tile
#define SA      132        // smem stride (floats), conflict-free for fragment gathers

// ---------------- scratch (allocation-free: device globals) ----------------
__device__ __align__(16) float g_agg[N_NODES * HID];   // self + neighbor sum
__device__ __align__(16) float g_h  [N_NODES * HID];   // conv output / BN output
__device__ __align__(16) float g_stats[4 * HID];       // [sum1, sumsq1, sum2, sumsq2]
__device__ __align__(16) float g_pool[NGRAPH * HID];
__device__            float g_cnt[NGRAPH];
__device__ int g_idx64;
__device__ int g_batch64;

// ---------------- helpers ----------------
__device__ __forceinline__ uint32_t f2tf(float f) {
    uint32_t u;
    asm("cvt.rna.tf32.f32 %0, %1;" : "=r"(u) : "f"(f));
    return u;
}
__device__ __forceinline__ void mma_tf32(float* c, const uint32_t* a, const uint32_t* b) {
    asm volatile(
        "mma.sync.aligned.m16n8k8.row.col.f32.tf32.tf32.f32 "
        "{%0,%1,%2,%3}, {%4,%5,%6,%7}, {%8,%9}, {%0,%1,%2,%3};"
        : "+f"(c[0]), "+f"(c[1]), "+f"(c[2]), "+f"(c[3])
        : "r"(a[0]), "r"(a[1]), "r"(a[2]), "r"(a[3]), "r"(b[0]), "r"(b[1]));
}

// ---------------- dtype detection ----------------
__global__ void detect_kernel(const void* eidx, const void* batch) {
    if (threadIdx.x == 0) {
        const long long* p = (const long long*)eidx;
        int ok = 1;
        for (int i = 0; i < 64; i++) { long long v = p[i]; if (v < 0 || v >= N_NODES) { ok = 0; break; } }
        g_idx64 = ok;
        const long long* q = (const long long*)batch;
        int ok2 = 1;
        for (int i = N_NODES / 2 - 64; i < N_NODES / 2; i++) { long long v = q[i]; if (v < 0 || v >= NGRAPH) { ok2 = 0; break; } }
        g_batch64 = ok2;
    }
}
__device__ __forceinline__ int load_index(const void* p, unsigned i, int is64) {
    return is64 ? (int)((const long long*)p)[i] : ((const int*)p)[i];
}

__global__ void zero_kernel() {
    int i = blockIdx.x * blockDim.x + threadIdx.x;
    if (i < NGRAPH * HID) g_pool[i] = 0.f;
    if (i < 4 * HID)      g_stats[i] = 0.f;
    if (i < NGRAPH)       g_cnt[i] = 0.f;
}
__global__ void copy_kernel(const float4* __restrict__ src) {
    int i = blockIdx.x * 256 + threadIdx.x;
    if (i < N_NODES * (HID / 4)) ((float4*)g_agg)[i] = src[i];
}
__global__ void scatter_kernel(const float* __restrict__ feat, const void* __restrict__ eidx) {
    unsigned idx = blockIdx.x * 256u + threadIdx.x;
    unsigned e = idx >> 5;
    if (e >= N_EDGES) return;
    unsigned c = idx & 31u;
    int is64 = g_idx64;
    int s = load_index(eidx, e, is64);
    int d = load_index(eidx, N_EDGES + e, is64);
    float4 v = ((const float4*)feat)[s * 32 + c];
    atomicAdd(((float4*)g_agg) + (d * 32 + c), v);
}

// ================= fused MLP: C = relu(A@Wa + ba)@Wb + bb  (mma.sync tf32) =================
// 256 threads = 8 warps in a 4(m) x 2(n) grid; warp tile 32x64; K=128 in 16 steps.
// SMEM floats: sA[128*SA] | sWa[128*SA] | sWb[128*SA] | ba[128] | bb[128]
__device__ __forceinline__ void warp_gemm_tf32(const float* __restrict__ sAp,
                                               const float* __restrict__ sW,
                                               int wm, int wn, int g, int tg,
                                               float acc[2][8][4])
{
#pragma unroll 4
    for (int kt = 0; kt < 16; kt++) {
        int k0 = kt * 8;
        uint32_t a[2][4];
#pragma unroll
        for (int mi = 0; mi < 2; mi++) {
            int r = wm + mi * 16 + g;
            a[mi][0] = __float_as_uint(sAp[(r    ) * SA + k0 + tg    ]);
            a[mi][1] = __float_as_uint(sAp[(r + 8) * SA + k0 + tg    ]);
            a[mi][2] = __float_as_uint(sAp[(r    ) * SA + k0 + tg + 4]);
            a[mi][3] = __float_as_uint(sAp[(r + 8) * SA + k0 + tg + 4]);
        }
        uint32_t b[8][2];
#pragma unroll
        for (int ni = 0; ni < 8; ni++) {
            int n = wn + ni * 8 + g;
            b[ni][0] = __float_as_uint(sW[(k0 + tg    ) * SA + n]);
            b[ni][1] = __float_as_uint(sW[(k0 + tg + 4) * SA + n]);
        }
#pragma unroll
        for (int mi = 0; mi < 2; mi++)
#pragma unroll
            for (int ni = 0; ni < 8; ni++)
                mma_tf32(acc[mi][ni], a[mi], b[ni]);
    }
}

__global__ void __launch_bounds__(256, 1) mlp_kernel(
    const float* __restrict__ A, const float* __restrict__ Wa, const float* __restrict__ ba,
    const float* __restrict__ Wb, const float* __restrict__ bb, float* __restrict__ C)
{
    extern __shared__ float sm[];
    float* sAp = sm;
    float* sWa = sm + 128 * SA;
    float* sWb = sWa + 128 * SA;
    float* sBa = sWb + 128 * SA;
    float* sBb = sBa + 128;

    int t = threadIdx.x;
    int wid = t >> 5, lane = t & 31, g = lane >> 2, tg = lane & 3;
    int wm = (wid & 3) * 32, wn = (wid >> 2) * 64;
    int row0 = blockIdx.x * MT;

    if (t < 128) { sBa[t] = ba[t]; sBb[t] = bb[t]; }

    // load + tf32-convert A, Wa, Wb
    {
        const float4* A4  = (const float4*)A;
        const float4* Wa4 = (const float4*)Wa;
        const float4* Wb4 = (const float4*)Wb;
#pragma unroll
        for (int i = 0; i < 16; i++) {
            int idx = t + i * 256;               // 0..4095
            int r = idx >> 5, c4 = idx & 31;
            float4 v = (row0 + r < N_NODES) ? A4[(size_t)(row0 + r) * 32 + c4]
                                            : make_float4(0.f, 0.f, 0.f, 0.f);
            uint4 u = make_uint4(f2tf(v.x), f2tf(v.y), f2tf(v.z), f2tf(v.w));
            *(uint4*)&sAp[r * SA + c4 * 4] = u;
            float4 wa = Wa4[idx];
            *(uint4*)&sWa[r * SA + c4 * 4] = make_uint4(f2tf(wa.x), f2tf(wa.y), f2tf(wa.z), f2tf(wa.w));
            float4 wb = Wb4[idx];
            *(uint4*)&sWb[r * SA + c4 * 4] = make_uint4(f2tf(wb.x), f2tf(wb.y), f2tf(wb.z), f2tf(wb.w));
        }
    }
    __syncthreads();

    // ---- GEMM 1: H = A @ Wa ----
    float acc[2][8][4];
#pragma unroll
    for (int mi = 0; mi < 2; mi++)
#pragma unroll
        for (int ni = 0; ni < 8; ni++)
#pragma unroll
            for (int q = 0; q < 4; q++) acc[mi][ni][q] = 0.f;

    warp_gemm_tf32(sAp, sWa, wm, wn, g, tg, acc);
    __syncthreads();   // everyone done reading sA

    // ---- epilogue 1: relu(H + ba) -> tf32 back into sA ----
#pragma unroll
    for (int mi = 0; mi < 2; mi++) {
        int r0 = wm + mi * 16 + g;
#pragma unroll
        for (int ni = 0; ni < 8; ni++) {
            int c0 = wn + ni * 8 + 2 * tg;
            float bx = sBa[c0], by = sBa[c0 + 1];
            sAp[(r0    ) * SA + c0    ] = __uint_as_float(f2tf(fmaxf(acc[mi][ni][0] + bx, 0.f)));
            sAp[(r0    ) * SA + c0 + 1] = __uint_as_float(f2tf(fmaxf(acc[mi][ni][1] + by, 0.f)));
            sAp[(r0 + 8) * SA + c0    ] = __uint_as_float(f2tf(fmaxf(acc[mi][ni][2] + bx, 0.f)));
            sAp[(r0 + 8) * SA + c0 + 1] = __uint_as_float(f2tf(fmaxf(acc[mi][ni][3] + by, 0.f)));
        }
    }
    __syncthreads();

    // ---- GEMM 2: out = H @ Wb ----
#pragma unroll
    for (int mi = 0; mi < 2; mi++)
#pragma unroll
        for (int ni = 0; ni < 8; ni++)
#pragma unroll
            for (int q = 0; q < 4; q++) acc[mi][ni][q] = 0.f;

    warp_gemm_tf32(sAp, sWb, wm, wn, g, tg, acc);

    // ---- epilogue 2: out + bb -> global ----
#pragma unroll
    for (int mi = 0; mi < 2; mi++) {
        int r0 = wm + mi * 16 + g;
#pragma unroll
        for (int ni = 0; ni < 8; ni++) {
            int c0 = wn + ni * 8 + 2 * tg;
            float bx = sBb[c0], by = sBb[c0 + 1];
            int rg0 = row0 + r0, rg1 = row0 + r0 + 8;
            if (rg0 < N_NODES) {
                float2 o = make_float2(acc[mi][ni][0] + bx, acc[mi][ni][1] + by);
                *(float2*)&C[(size_t)rg0 * HID + c0] = o;
            }
            if (rg1 < N_NODES) {
                float2 o = make_float2(acc[mi][ni][2] + bx, acc[mi][ni][3] + by);
                *(float2*)&C[(size_t)rg1 * HID + c0] = o;
            }
        }
    }
}

// ================= BN / stats / pool / head =================
__global__ void colstats_kernel(const float* __restrict__ h, int stat_off) {
    int f = threadIdx.x;
    float s = 0.f, q = 0.f;
    for (int r = blockIdx.x; r < N_NODES; r += gridDim.x) {
        float v = h[(size_t)r * HID + f];
        s += v; q += v * v;
    }
    atomicAdd(&g_stats[stat_off + f], s);
    atomicAdd(&g_stats[stat_off + HID + f], q);
}

__global__ void bn_apply1_kernel(const float* __restrict__ gamma, const float* __restrict__ beta) {
    int i = blockIdx.x * 256 + threadIdx.x;
    if (i >= N_NODES * 32) return;
    int c4 = i & 31;
    const float inv_n = 1.f / (float)N_NODES;
    float4 sum4 = ((const float4*)g_stats)[c4];
    float4 sq4  = ((const float4*)g_stats)[32 + c4];
    float4 gm4  = ((const float4*)gamma)[c4];
    float4 bt4  = ((const float4*)beta)[c4];
    float4 v = ((float4*)g_h)[i];
    float4 y;
    float m = sum4.x * inv_n, var = sq4.x * inv_n - m * m;
    y.x = fmaxf((v.x - m) * rsqrtf(var + BN_EPS) * gm4.x + bt4.x, 0.f);
    m = sum4.y * inv_n; var = sq4.y * inv_n - m * m;
    y.y = fmaxf((v.y - m) * rsqrtf(var + BN_EPS) * gm4.y + bt4.y, 0.f);
    m = sum4.z * inv_n; var = sq4.z * inv_n - m * m;
    y.z = fmaxf((v.z - m) * rsqrtf(var + BN_EPS) * gm4.z + bt4.z, 0.f);
    m = sum4.w * inv_n; var = sq4.w * inv_n - m * m;
    y.w = fmaxf((v.w - m) * rsqrtf(var + BN_EPS) * gm4.w + bt4.w, 0.f);
    ((float4*)g_h)[i] = y;
    ((float4*)g_agg)[i] = y;
}

__global__ void bn_apply2_kernel(const float* __restrict__ gamma, const float* __restrict__ beta,
                                 const void* __restrict__ batch) {
    int i = blockIdx.x * 256 + threadIdx.x;
    if (i >= N_NODES * 32) return;
    int c4 = i & 31;
    int row = i >> 5;
    const float inv_n = 1.f / (float)N_NODES;
    float4 sum4 = ((const float4*)g_stats)[64 + c4];
    float4 sq4  = ((const float4*)g_stats)[96 + c4];
    float4 gm4  = ((const float4*)gamma)[c4];
    float4 bt4  = ((const float4*)beta)[c4];
    float4 v = ((float4*)g_h)[i];
    float4 y;
    float m = sum4.x * inv_n, var = sq4.x * inv_n - m * m;
    y.x = fmaxf((v.x - m) * rsqrtf(var + BN_EPS) * gm4.x + bt4.x, 0.f);
    m = sum4.y * inv_n; var = sq4.y * inv_n - m * m;
    y.y = fmaxf((v.y - m) * rsqrtf(var + BN_EPS) * gm4.y + bt4.y, 0.f);
    m = sum4.z * inv_n; var = sq4.z * inv_n - m * m;
    y.z = fmaxf((v.z - m) * rsqrtf(var + BN_EPS) * gm4.z + bt4.z, 0.f);
    m = sum4.w * inv_n; var = sq4.w * inv_n - m * m;
    y.w = fmaxf((v.w - m) * rsqrtf(var + BN_EPS) * gm4.w + bt4.w, 0.f);
    int b = load_index(batch, (unsigned)row, g_batch64);
    atomicAdd(((float4*)g_pool) + (b * 32 + c4), y);
}

__global__ void counts_kernel(const void* __restrict__ batch) {
    __shared__ int hist[NGRAPH];
    if (threadIdx.x < NGRAPH) hist[threadIdx.x] = 0;
    __syncthreads();
    int is64 = g_batch64;
    for (int i = blockIdx.x * 256 + threadIdx.x; i < N_NODES; i += gridDim.x * 256)
        atomicAdd(&hist[load_index(batch, (unsigned)i, is64)], 1);
    __syncthreads();
    if (threadIdx.x < NGRAPH && hist[threadIdx.x])
        atomicAdd(&g_cnt[threadIdx.x], (float)hist[threadIdx.x]);
}

__global__ void head_kernel(const float* __restrict__ Wlin, const float* __restrict__ blin,
                            float* __restrict__ out) {
    __shared__ float p[HID];
    __shared__ float logit[NCLS];
    int g = blockIdx.x;
    float c = fmaxf(g_cnt[g], 1.0f);
    p[threadIdx.x] = g_pool[g * HID + threadIdx.x] / c;
    __syncthreads();
    if (threadIdx.x < NCLS) {
        float s = blin[threadIdx.x];
        for (int k = 0; k < HID; k++) s += p[k] * Wlin[k * NCLS + threadIdx.x];
        logit[threadIdx.x] = s;
    }
    __syncthreads();
    if (threadIdx.x == 0) {
        float m = -1e30f;
        for (int i = 0; i < NCLS; i++) m = fmaxf(m, logit[i]);
        float se = 0.f;
        for (int i = 0; i < NCLS; i++) se += expf(logit[i] - m);
        float lse = m + logf(se);
        for (int i = 0; i < NCLS; i++) out[g * NCLS + i] = logit[i] - lse;
    }
}

// ================= launch =================
extern "C" void kernel_launch(void* const* d_in, const int* in_sizes, int n_in,
                              void* d_out, int out_size) {
    const float* x     = (const float*)d_in[0];
    const void*  eidx  = d_in[1];
    const void*  batch = d_in[2];
    const float* W1a = (const float*)d_in[3];
    const float* b1a = (const float*)d_in[4];
    const float* W1b = (const float*)d_in[5];
    const float* b1b = (const float*)d_in[6];
    const float* gamma1 = (const float*)d_in[7];
    const float* beta1  = (const float*)d_in[8];
    const float* W2a = (const float*)d_in[9];
    const float* b2a = (const float*)d_in[10];
    const float* W2b = (const float*)d_in[11];
    const float* b2b = (const float*)d_in[12];
    const float* gamma2 = (const float*)d_in[13];
    const float* beta2  = (const float*)d_in[14];
    const float* Wlin = (const float*)d_in[15];
    const float* blin = (const float*)d_in[16];
    float* out = (float*)d_out;

    float *p_agg, *p_h;
    cudaGetSymbolAddress((void**)&p_agg, g_agg);
    cudaGetSymbolAddress((void**)&p_h,   g_h);

    const int SMEM_MLP = (3 * 128 * SA + 256) * sizeof(float);   // ~204 KB
    cudaFuncSetAttribute(mlp_kernel, cudaFuncAttributeMaxDynamicSharedMemorySize, SMEM_MLP);

    const int EW_BLOCKS  = (N_NODES * 32 + 255) / 256;
    const int SC_BLOCKS  = (N_EDGES * 32 + 255) / 256;
    const int MLP_BLOCKS = (N_NODES + MT - 1) / MT;

    detect_kernel<<<1, 32>>>(eidx, batch);
    zero_kernel<<<64, 256>>>();

    // ---- conv1 ----
    copy_kernel<<<EW_BLOCKS, 256>>>((const float4*)x);
    scatter_kernel<<<SC_BLOCKS, 256>>>(x, eidx);
    mlp_kernel<<<MLP_BLOCKS, 256, SMEM_MLP>>>(p_agg, W1a, b1a, W1b, b1b, p_h);
    colstats_kernel<<<1024, 128>>>(p_h, 0);
    bn_apply1_kernel<<<EW_BLOCKS, 256>>>(gamma1, beta1);

    // ---- conv2 ----
    scatter_kernel<<<SC_BLOCKS, 256>>>(p_h, eidx);
    mlp_kernel<<<MLP_BLOCKS, 256, SMEM_MLP>>>(p_agg, W2a, b2a, W2b, b2b, p_h);
    colstats_kernel<<<1024, 128>>>(p_h, 2 * HID);
    counts_kernel<<<128, 256>>>(batch);
    bn_apply2_kernel<<<EW_BLOCKS, 256>>>(gamma2, beta2, batch);

    // ---- head ----
    head_kernel<<<NGRAPH, HID>>>(Wlin, blin, out);
}